// round 17
// baseline (speedup 1.0000x reference)
#include <cuda_runtime.h>
#include <cuda_fp16.h>
#include <cuda_bf16.h>

#define N_NODES 100000
#define N_EDGES 6400000
#define F_IN 5
#define F_HID 5
#define F_OUT 10

// 16B rows: 8 f16 lanes per node.
// layer-1 source row: [x0,x1][x2,x3][x4,1.0][0,0]   (lane 5 = degree increment)
// layer-2 source row: [g0,g1][g2,g3][g4,0 ][0,0]    (g = h - 0.5, centered)
__device__ __align__(16) uint4 g_xpack[N_NODES];
__device__ __align__(16) uint4 g_hpack[N_NODES];
__device__ __align__(16) uint4 g_agg[N_NODES];
__device__ __align__(16) float g_h8[N_NODES * 8];   // full-precision h for self term
__device__ float g_deg[N_NODES];

__device__ __forceinline__ float fast_sigmoid(float x) {
    return 1.0f / (1.0f + __expf(-x));
}

// ONE 16-byte packed-half atomic per edge: 8 f16 lanes.
__device__ __forceinline__ void red_add_v4_f16x2(uint4* addr, uint4 v) {
    asm volatile("red.global.add.noftz.v4.f16x2 [%0], {%1,%2,%3,%4};"
                 :: "l"(addr), "r"(v.x), "r"(v.y), "r"(v.z), "r"(v.w) : "memory");
}

__device__ __forceinline__ unsigned pack_h2(float a, float b) {
    __half2 h = __floats2half2_rn(a, b);
    return *reinterpret_cast<unsigned*>(&h);
}
__device__ __forceinline__ float2 unpack_h2(unsigned u) {
    __half2 h = *reinterpret_cast<__half2*>(&u);
    return __half22float2(h);
}

// ---- init: encode x rows (f16), zero accumulators ----
__global__ __launch_bounds__(256) void init_kernel(const float* __restrict__ x) {
    int i = blockIdx.x * blockDim.x + threadIdx.x;
    if (i >= N_NODES) return;
    const float* xr = x + (size_t)i * F_IN;
    uint4 p;
    p.x = pack_h2(xr[0], xr[1]);
    p.y = pack_h2(xr[2], xr[3]);
    p.z = pack_h2(xr[4], 1.0f);     // lane5 = degree increment
    p.w = 0u;
    g_xpack[i] = p;
    g_agg[i] = make_uint4(0u, 0u, 0u, 0u);
}

// ---- edge pass: gather 16B source row, ONE v4.f16x2 RED into dst row ----
template <bool LAYER1>
__global__ __launch_bounds__(256) void edge_kernel(const int* __restrict__ src,
                                                   const int* __restrict__ dst) {
    int t = blockIdx.x * blockDim.x + threadIdx.x;
    int e = t * 4;
    if (e >= N_EDGES) return;
    const int4 s4 = *reinterpret_cast<const int4*>(src + e);
    const int4 d4 = *reinterpret_cast<const int4*>(dst + e);
    const uint4* tab = LAYER1 ? g_xpack : g_hpack;

    int ss[4] = {s4.x, s4.y, s4.z, s4.w};
    int dd[4] = {d4.x, d4.y, d4.z, d4.w};
#pragma unroll
    for (int k = 0; k < 4; k++) {
        uint4 v = __ldg(&tab[ss[k]]);
        red_add_v4_f16x2(&g_agg[dd[k]], v);
    }
}

// ---- layer-1 epilogue: decode f16 sums + exact deg, GEMV + sigmoid,
//      write full-precision h + centered f16 h row, reset agg ----
__global__ __launch_bounds__(256) void node1_kernel(const float* __restrict__ x,
                                                    const float* __restrict__ Ws,
                                                    const float* __restrict__ Wn,
                                                    const float* __restrict__ b) {
    int v = blockIdx.x * blockDim.x + threadIdx.x;
    if (v >= N_NODES) return;
    uint4 a = g_agg[v];
    float2 s01 = unpack_h2(a.x);
    float2 s23 = unpack_h2(a.y);
    float2 s4d = unpack_h2(a.z);
    float fdeg = s4d.y;                       // exact integer count in f16
    float inv = 1.0f / fmaxf(fdeg, 1.0f);

    float av[F_IN] = {s01.x * inv, s01.y * inv, s23.x * inv, s23.y * inv, s4d.x * inv};

    const float* xr = x + (size_t)v * F_IN;
    float xv[F_IN];
#pragma unroll
    for (int f = 0; f < F_IN; f++) xv[f] = __ldg(xr + f);

    float h[F_HID];
#pragma unroll
    for (int j = 0; j < F_HID; j++) {
        float acc = b[j];
#pragma unroll
        for (int f = 0; f < F_IN; f++) {
            acc = fmaf(xv[f], Ws[f * F_HID + j], acc);
            acc = fmaf(av[f], Wn[f * F_HID + j], acc);
        }
        h[j] = fast_sigmoid(acc);
    }
    // full-precision h for the self term
    *reinterpret_cast<float4*>(g_h8 + (size_t)v * 8) = make_float4(h[0], h[1], h[2], h[3]);
    g_h8[(size_t)v * 8 + 4] = h[4];
    // centered f16 row for layer-2 aggregation (g = h - 0.5 keeps sums zero-mean)
    uint4 p;
    p.x = pack_h2(h[0] - 0.5f, h[1] - 0.5f);
    p.y = pack_h2(h[2] - 0.5f, h[3] - 0.5f);
    p.z = pack_h2(h[4] - 0.5f, 0.0f);
    p.w = 0u;
    g_hpack[v] = p;
    g_deg[v] = fdeg;
    g_agg[v] = make_uint4(0u, 0u, 0u, 0u);    // reset for layer 2
}

// ---- layer-2 epilogue: mean(h) = sum(g)/deg + 0.5 ----
__global__ __launch_bounds__(256) void node2_kernel(const float* __restrict__ Ws,
                                                    const float* __restrict__ Wn,
                                                    const float* __restrict__ b,
                                                    float* __restrict__ out) {
    int v = blockIdx.x * blockDim.x + threadIdx.x;
    if (v >= N_NODES) return;
    uint4 a = g_agg[v];
    float2 s01 = unpack_h2(a.x);
    float2 s23 = unpack_h2(a.y);
    float2 s4_ = unpack_h2(a.z);
    float fdeg = g_deg[v];
    float inv = 1.0f / fmaxf(fdeg, 1.0f);
    float bias = (fdeg > 0.0f) ? 0.5f : 0.0f;   // isolated nodes: mean = 0

    float av[F_HID];
    av[0] = s01.x * inv + bias;
    av[1] = s01.y * inv + bias;
    av[2] = s23.x * inv + bias;
    av[3] = s23.y * inv + bias;
    av[4] = s4_.x * inv + bias;

    float hv[F_HID];
#pragma unroll
    for (int f = 0; f < F_HID; f++) hv[f] = g_h8[(size_t)v * 8 + f];

#pragma unroll
    for (int j = 0; j < F_OUT; j++) {
        float acc = b[j];
#pragma unroll
        for (int f = 0; f < F_HID; f++) {
            acc = fmaf(hv[f], Ws[f * F_OUT + j], acc);
            acc = fmaf(av[f], Wn[f * F_OUT + j], acc);
        }
        out[(size_t)v * F_OUT + j] = fast_sigmoid(acc);
    }
}

extern "C" void kernel_launch(void* const* d_in, const int* in_sizes, int n_in,
                              void* d_out, int out_size) {
    const float* x   = (const float*)d_in[0];
    const int*   src = (const int*)d_in[1];
    const int*   dst = (const int*)d_in[2];
    const float* Ws1 = (const float*)d_in[3];
    const float* Wn1 = (const float*)d_in[4];
    const float* b1  = (const float*)d_in[5];
    const float* Ws2 = (const float*)d_in[6];
    const float* Wn2 = (const float*)d_in[7];
    const float* b2  = (const float*)d_in[8];
    float* out = (float*)d_out;

    const int nb_nodes  = (N_NODES + 255) / 256;
    const int nb_edges4 = (N_EDGES / 4 + 255) / 256;

    init_kernel<<<nb_nodes, 256>>>(x);
    edge_kernel<true><<<nb_edges4, 256>>>(src, dst);
    node1_kernel<<<nb_nodes, 256>>>(x, Ws1, Wn1, b1);
    edge_kernel<false><<<nb_edges4, 256>>>(src, dst);
    node2_kernel<<<nb_nodes, 256>>>(Ws2, Wn2, b2, out);
}